// round 2
// baseline (speedup 1.0000x reference)
#include <cuda_runtime.h>

#define NEG (-1e30f)

constexpr int B  = 8;
constexpr int T  = 200;
constexpr int U1 = 101;
constexpr int V  = 512;
constexpr int U  = U1 - 1;
constexpr int D  = T + U1 - 1;           // 300 anti-diagonals
constexpr int NCELL = B * T * U1;        // 161600

// Skewed (diagonal-major) log-prob tables: [b][d = t+u][u]
__device__ float g_bsk[B * D * U1];
__device__ float g_esk[B * D * U1];
__device__ float g_loss[B];

__device__ __forceinline__ float logaddexpf_(float a, float b) {
    float mx = fmaxf(a, b);
    float mn = fminf(a, b);
    return mx + log1pf(__expf(mn - mx));
}

// One warp per (b,t,u) cell: logsumexp over V=512, emit blank/label log-probs
// into the skewed tables.
__global__ void __launch_bounds__(256) k_lse(const float* __restrict__ logits,
                                             const int*   __restrict__ targets) {
    int gw   = (blockIdx.x * blockDim.x + threadIdx.x) >> 5;
    int lane = threadIdx.x & 31;
    if (gw >= NCELL) return;

    int u = gw % U1;
    int t = (gw / U1) % T;
    int b = gw / (U1 * T);

    const float4* p = reinterpret_cast<const float4*>(logits) + (size_t)gw * (V / 4);
    float4 v0 = p[lane];
    float4 v1 = p[lane + 32];
    float4 v2 = p[lane + 64];
    float4 v3 = p[lane + 96];

    // local max over 16 elems
    float m = fmaxf(fmaxf(fmaxf(v0.x, v0.y), fmaxf(v0.z, v0.w)),
                    fmaxf(fmaxf(fmaxf(v1.x, v1.y), fmaxf(v1.z, v1.w)),
                          fmaxf(fmaxf(fmaxf(v2.x, v2.y), fmaxf(v2.z, v2.w)),
                                fmaxf(fmaxf(v3.x, v3.y), fmaxf(v3.z, v3.w)))));
#pragma unroll
    for (int o = 16; o; o >>= 1) m = fmaxf(m, __shfl_xor_sync(0xffffffffu, m, o));

    float s = __expf(v0.x - m) + __expf(v0.y - m) + __expf(v0.z - m) + __expf(v0.w - m)
            + __expf(v1.x - m) + __expf(v1.y - m) + __expf(v1.z - m) + __expf(v1.w - m)
            + __expf(v2.x - m) + __expf(v2.y - m) + __expf(v2.z - m) + __expf(v2.w - m)
            + __expf(v3.x - m) + __expf(v3.y - m) + __expf(v3.z - m) + __expf(v3.w - m);
#pragma unroll
    for (int o = 16; o; o >>= 1) s += __shfl_xor_sync(0xffffffffu, s, o);

    float lse = m + __logf(s);

    size_t base = ((size_t)b * D + (t + u)) * U1 + u;

    // blank = vocab index 0, owned by lane 0 (v0.x)
    if (lane == 0) g_bsk[base] = v0.x - lse;

    // emit = vocab index targets[b, u+1]  (only defined for u < U)
    int lab = (u < U) ? targets[b * U1 + u + 1] : -1;
    if (lab >= 0) {
        int chunk = lab >> 2;            // which float4 (0..127)
        if ((chunk & 31) == lane) {
            int j = chunk >> 5, c = lab & 3;
            float4 vv = (j == 0) ? v0 : (j == 1) ? v1 : (j == 2) ? v2 : v3;
            float ev  = (c == 0) ? vv.x : (c == 1) ? vv.y : (c == 2) ? vv.z : vv.w;
            g_esk[base] = ev - lse;
        }
    }
}

// Anti-diagonal alpha recurrence. One CTA per batch element.
__global__ void __launch_bounds__(128) k_dp(const int* __restrict__ fbank_len,
                                            const int* __restrict__ text_len) {
    int b = blockIdx.x;
    int u = threadIdx.x;

    __shared__ float P[U1];

    const float* bsk = g_bsk + (size_t)b * D * U1;
    const float* esk = g_esk + (size_t)b * D * U1;

    int lab_len = text_len[b] - 1;
    int dfin    = fbank_len[b] - 1 + lab_len;

    if (u < U1) P[u] = (u == 0) ? 0.0f : NEG;

    float afin = NEG;

    // prefetch diagonal row 0 (used at d=1)
    float nb = NEG, ne = NEG;
    if (u < U1) nb = bsk[u];
    if (u >= 1 && u - 1 < U) ne = esk[u - 1];
    __syncthreads();

    for (int d = 1; d < D; ++d) {
        float cb = nb, ce = ne;
        float pu = (u < U1) ? P[u] : NEG;
        float pm = (u >= 1 && u < U1) ? P[u - 1] : NEG;

        // prefetch row d for next iteration (independent of DP state)
        if (d < D - 1) {
            int rowN = d * U1;
            if (u < U1) nb = bsk[rowN + u];
            if (u >= 1 && u - 1 < U) ne = esk[rowN + u - 1];
        }

        float nv = NEG;
        int t = d - u;
        if (u < U1 && t >= 0 && t < T) {
            float stay = (t >= 1) ? pu + cb : NEG;              // alpha[t-1,u] + blank[t-1,u]
            float mv   = (u >= 1 && u - 1 < U) ? pm + ce : NEG;  // alpha[t,u-1] + emit[t,u-1]
            nv = logaddexpf_(stay, mv);
        }
        __syncthreads();
        if (u < U1) P[u] = nv;
        if (d == dfin && u == lab_len) afin = nv;
        __syncthreads();
    }

    if (u == lab_len)
        g_loss[b] = -(afin + bsk[dfin * U1 + lab_len]);
}

__global__ void k_mean(float* __restrict__ out) {
    float s = 0.0f;
#pragma unroll
    for (int i = 0; i < B; ++i) s += g_loss[i];
    *out = s / (float)B;
}

extern "C" void kernel_launch(void* const* d_in, const int* in_sizes, int n_in,
                              void* d_out, int out_size) {
    const float* logits  = (const float*)d_in[0];
    const int*   targets = (const int*)d_in[1];
    const int*   fb      = (const int*)d_in[2];
    const int*   tl      = (const int*)d_in[3];

    int blocks = (NCELL * 32 + 255) / 256;  // one warp per cell, 8 warps/block
    k_lse<<<blocks, 256>>>(logits, targets);
    k_dp<<<B, 128>>>(fb, tl);
    k_mean<<<1, 1>>>((float*)d_out);
}

// round 3
// speedup vs baseline: 1.8320x; 1.8320x over previous
#include <cuda_runtime.h>

#define NEG (-1e30f)

constexpr int B  = 8;
constexpr int T  = 200;
constexpr int U1 = 101;
constexpr int V  = 512;
constexpr int U  = U1 - 1;
constexpr int D  = T + U1 - 1;           // 300 anti-diagonals
constexpr int NCELL = B * T * U1;        // 161600
constexpr int SB = 102;                  // padded smem row stride (anti-diagonal conflict-free)

// Unskewed log-prob tables: [b][t][u]
__device__ float g_blank[B * T * U1];
__device__ float g_emit [B * T * U];
__device__ float g_loss [B];

__device__ __forceinline__ float logaddexpf_(float a, float b) {
    float mx = fmaxf(a, b);
    float mn = fminf(a, b);
    return mx + __logf(1.0f + __expf(mn - mx));
}

// One warp per (b,t,u) cell: logsumexp over V=512, emit blank/label log-probs.
__global__ void __launch_bounds__(256) k_lse(const float* __restrict__ logits,
                                             const int*   __restrict__ targets) {
    int gw   = (blockIdx.x * blockDim.x + threadIdx.x) >> 5;
    int lane = threadIdx.x & 31;
    if (gw >= NCELL) return;

    int u = gw % U1;
    int t = (gw / U1) % T;
    int b = gw / (U1 * T);

    const float4* p = reinterpret_cast<const float4*>(logits) + (size_t)gw * (V / 4);
    float4 v0 = p[lane];
    float4 v1 = p[lane + 32];
    float4 v2 = p[lane + 64];
    float4 v3 = p[lane + 96];

    float m = fmaxf(fmaxf(fmaxf(v0.x, v0.y), fmaxf(v0.z, v0.w)),
                    fmaxf(fmaxf(fmaxf(v1.x, v1.y), fmaxf(v1.z, v1.w)),
                          fmaxf(fmaxf(fmaxf(v2.x, v2.y), fmaxf(v2.z, v2.w)),
                                fmaxf(fmaxf(v3.x, v3.y), fmaxf(v3.z, v3.w)))));
#pragma unroll
    for (int o = 16; o; o >>= 1) m = fmaxf(m, __shfl_xor_sync(0xffffffffu, m, o));

    float s = __expf(v0.x - m) + __expf(v0.y - m) + __expf(v0.z - m) + __expf(v0.w - m)
            + __expf(v1.x - m) + __expf(v1.y - m) + __expf(v1.z - m) + __expf(v1.w - m)
            + __expf(v2.x - m) + __expf(v2.y - m) + __expf(v2.z - m) + __expf(v2.w - m)
            + __expf(v3.x - m) + __expf(v3.y - m) + __expf(v3.z - m) + __expf(v3.w - m);
#pragma unroll
    for (int o = 16; o; o >>= 1) s += __shfl_xor_sync(0xffffffffu, s, o);

    float lse = m + __logf(s);

    // blank = vocab index 0, owned by lane 0 (v0.x)
    if (lane == 0) g_blank[(size_t)b * T * U1 + t * U1 + u] = v0.x - lse;

    // emit = vocab index targets[b, u+1]  (only defined for u < U)
    int lab = (u < U) ? targets[b * U1 + u + 1] : -1;
    if (lab >= 0) {
        int chunk = lab >> 2;            // which float4 (0..127)
        if ((chunk & 31) == lane) {
            int j = chunk >> 5, c = lab & 3;
            float4 vv = (j == 0) ? v0 : (j == 1) ? v1 : (j == 2) ? v2 : v3;
            float ev  = (c == 0) ? vv.x : (c == 1) ? vv.y : (c == 2) ? vv.z : vv.w;
            g_emit[(size_t)b * T * U + t * U + u] = ev - lse;
        }
    }
}

// Anti-diagonal alpha recurrence, fully smem-resident. One CTA per batch element.
// Dynamic smem: blank [T][SB] + emit [T][SB] + two alpha rows.
constexpr int SMEM_DP = (2 * T * SB + 2 * (U1 + 3)) * (int)sizeof(float);

__global__ void __launch_bounds__(256) k_dp(const int* __restrict__ fbank_len,
                                            const int* __restrict__ text_len) {
    extern __shared__ float sm[];
    float* smb = sm;                 // blank  [T][SB]
    float* sme = sm + T * SB;        // emit   [T][SB]
    float* P   = sme + T * SB;       // alpha row (U1+3)
    float* Q   = P + (U1 + 3);       // alpha row (U1+3)

    int b   = blockIdx.x;
    int tid = threadIdx.x;
    int u   = tid;

    const float* gb = g_blank + (size_t)b * T * U1;
    const float* ge = g_emit  + (size_t)b * T * U;

    // Stage tables into smem (coalesced global reads; padded smem rows)
    for (int i = tid; i < T * U1; i += 256) smb[(i / U1) * SB + (i % U1)] = gb[i];
    for (int i = tid; i < T * U;  i += 256) sme[(i / U)  * SB + (i % U)]  = ge[i];

    int lab_len = text_len[b] - 1;
    int dfin    = fbank_len[b] - 1 + lab_len;

    if (u < U1) P[u] = (u == 0) ? 0.0f : NEG;
    __syncthreads();

    float afin = NEG;

#pragma unroll 4
    for (int d = 1; d < D; ++d) {
        if (u < U1) {
            float nv = NEG;
            int t = d - u;
            if (t >= 0 && t < T) {
                // stay: alpha[t-1,u] + blank[t-1,u]   (skewed smem read, conflict-free)
                float stay = (t >= 1) ? P[u] + smb[(t - 1) * SB + u] : NEG;
                // move: alpha[t,u-1] + emit[t,u-1]
                float mv = (u >= 1) ? P[u - 1] + sme[t * SB + (u - 1)] : NEG;
                nv = logaddexpf_(stay, mv);
            }
            Q[u] = nv;
            if (d == dfin && u == lab_len) afin = nv;
        }
        __syncthreads();
        float* tp = P; P = Q; Q = tp;   // double buffer: one barrier per step
    }

    if (u == lab_len)
        g_loss[b] = -(afin + smb[(fbank_len[b] - 1) * SB + lab_len]);
}

__global__ void k_mean(float* __restrict__ out) {
    float s = 0.0f;
#pragma unroll
    for (int i = 0; i < B; ++i) s += g_loss[i];
    *out = s / (float)B;
}

extern "C" void kernel_launch(void* const* d_in, const int* in_sizes, int n_in,
                              void* d_out, int out_size) {
    const float* logits  = (const float*)d_in[0];
    const int*   targets = (const int*)d_in[1];
    const int*   fb      = (const int*)d_in[2];
    const int*   tl      = (const int*)d_in[3];

    cudaFuncSetAttribute(k_dp, cudaFuncAttributeMaxDynamicSharedMemorySize, SMEM_DP);

    int blocks = (NCELL * 32 + 255) / 256;  // one warp per cell, 8 warps/block
    k_lse<<<blocks, 256>>>(logits, targets);
    k_dp<<<B, 256, SMEM_DP>>>(fb, tl);
    k_mean<<<1, 1>>>((float*)d_out);
}